// round 7
// baseline (speedup 1.0000x reference)
#include <cuda_runtime.h>
#include <cuda_fp16.h>
#include <cstring>

// CombinedPriorityLoss: 0.1*MSE + 0.9*pairwise-rank + 0.1*diversity
// fp16x2 pair engine, single mask-select accumulator (pred pre-scaled by 0.1),
// 16 blocks/SM (single wave), deterministic last-block finalize.

#define MARGIN 0.2f

constexpr int T = 128;            // tile size == block size
constexpr int MAXT = 128;         // N <= 16384
constexpr int MAXB = MAXT * (MAXT + 1) / 2;

__device__ float  g_partial[MAXB];   // combined A + 0.1*B per block
__device__ float  g_moms[MAXT][5];
__device__ unsigned g_ticket = 0;

__device__ __forceinline__ __half2 u2h(unsigned u) {
    __half2 h; memcpy(&h, &u, 4); return h;
}
__device__ __forceinline__ unsigned h2u(__half2 h) {
    unsigned u; memcpy(&u, &h, 4); return u;
}

__global__ __launch_bounds__(T, 16)
void fused_kernel(const float* __restrict__ pred,
                  const float* __restrict__ tgt,
                  int N, int nt, float* __restrict__ out) {
    const int bid = blockIdx.x;
    const int nblocks = gridDim.x;
    const int tid = threadIdx.x;
    const int lane = tid & 31;
    const int wid  = tid >> 5;

    // decode upper-triangle (ti <= tj)
    int ti = (int)((2.0 * nt + 1.0 -
                    sqrt((2.0 * nt + 1.0) * (2.0 * nt + 1.0) - 8.0 * bid)) * 0.5);
    while ((ti + 1) * nt - ((ti + 1) * ti) / 2 <= bid) ti++;
    while (ti * nt - (ti * (ti - 1)) / 2 > bid) ti--;
    const int tj = ti + (bid - (ti * nt - (ti * (ti - 1)) / 2));

    __shared__ uint4 sP[T / 8];   // 128 x fp16(-0.1*pred[j])
    __shared__ uint4 sT[T / 8];   // 128 x fp16(-tgt[j])
    __shared__ float red[4][8];
    __shared__ int s_last;

    {
        int j = tj * T + tid;
        // finite pad: contributes exactly 0 in every branch
        float pj = (j < N) ? pred[j] : 30000.f;
        float tv = (j < N) ? tgt[j]  : 30000.f;
        ((__half*)sP)[tid] = __float2half_rn(-0.1f * pj);
        ((__half*)sT)[tid] = __float2half_rn(-tv);
    }
    __syncthreads();

    int i = ti * T + tid;
    {
        float pif = (i < N) ? pred[i] : 30000.f;
        float tif = (i < N) ? tgt[i]  : 30000.f;
        // scoped so fp32 copies die before the inner loop
        unsigned pi2_ = h2u(__half2half2(__float2half_rn(0.1f * pif)));
        unsigned ti2_ = h2u(__half2half2(__float2half_rn(tif)));

        const __half2 M2   = __float2half2_rn(MARGIN);
        const __half2 Z2   = __float2half2_rn(0.f);
        const __half2 TEN2 = __float2half2_rn(10.f);

        __half2 acc[4];
        #pragma unroll
        for (int q = 0; q < 4; q++) acc[q] = Z2;

        // per half2 (2 pairs):
        // dp'' = 0.1*(pi-pj); dt = ti-tj
        // qx'' = (dt>0 ? -dp'' : dp'') via sign LOP3
        // r = max(10*qx'' + M, 0)   (== relu branch value)
        // v = |dt|>M ? r : |dp''|   (|dp''| == 0.1*|dp| == mid branch value)
        #define PAIR2(vpu, vtu, q) {                                          \
            unsigned dpu = h2u(__hadd2(u2h(pi2_), u2h(vpu)));                 \
            unsigned dtu = h2u(__hadd2(u2h(ti2_), u2h(vtu)));                 \
            unsigned qxu = dpu ^ 0x80008000u ^ (dtu & 0x80008000u);           \
            __half2 r2 = __hmax2(__hfma2(u2h(qxu), TEN2, M2), Z2);            \
            unsigned m = __hgt2_mask(u2h(dtu & 0x7FFF7FFFu), M2);             \
            unsigned vs = (h2u(r2) & m) | ((dpu & 0x7FFF7FFFu) & ~m);         \
            acc[q] = __hadd2(acc[q], u2h(vs)); }

        #pragma unroll 4
        for (int k = 0; k < T / 8; k++) {
            uint4 vp = sP[k];
            uint4 vt = sT[k];
            PAIR2(vp.x, vt.x, 0);
            PAIR2(vp.y, vt.y, 1);
            PAIR2(vp.z, vt.z, 2);
            PAIR2(vp.w, vt.w, 3);
        }
        #undef PAIR2

        float accC = 0.f;
        #pragma unroll
        for (int q = 0; q < 4; q++)
            accC += __low2float(acc[q]) + __high2float(acc[q]);
        float w = (ti == tj) ? 1.f : 2.f;
        accC *= w;

        // block reduction (4 warps)
        #pragma unroll
        for (int o = 16; o; o >>= 1)
            accC += __shfl_down_sync(0xffffffffu, accC, o);
        if (lane == 0) red[wid][0] = accC;
    }
    __syncthreads();
    if (tid == 0) {
        float a = 0.f;
        #pragma unroll
        for (int w2 = 0; w2 < 4; w2++) a += red[w2][0];
        g_partial[bid] = a;
    }
    __syncthreads();

    // diagonal blocks: O(N) fp32 moment partials (reload inputs)
    if (ti == tj) {
        float p = 0.f, t = 0.f;
        if (i < N) { p = pred[i]; t = tgt[i]; }
        float d = p - t;
        float m[5] = { d * d, p, p * p, t, t * t };
        #pragma unroll
        for (int k = 0; k < 5; k++) {
            float v = m[k];
            #pragma unroll
            for (int o = 16; o; o >>= 1) v += __shfl_down_sync(0xffffffffu, v, o);
            if (lane == 0) red[wid][k] = v;
        }
        __syncthreads();
        if (tid == 0) {
            #pragma unroll
            for (int k = 0; k < 5; k++) {
                float v = 0.f;
                #pragma unroll
                for (int w2 = 0; w2 < 4; w2++) v += red[w2][k];
                g_moms[ti][k] = v;
            }
        }
    }

    // ---- deterministic last-block finalize ----
    __threadfence();
    if (tid == 0) {
        unsigned t = atomicAdd(&g_ticket, 1u);
        s_last = (t == (unsigned)(nblocks - 1));
    }
    __syncthreads();
    if (!s_last) return;

    double aC = 0.0;
    for (int b = tid; b < nblocks; b += T) aC += (double)g_partial[b];
    double mm[5] = {0, 0, 0, 0, 0};
    for (int b = tid; b < nt; b += T) {
        #pragma unroll
        for (int k = 0; k < 5; k++) mm[k] += (double)g_moms[b][k];
    }

    __shared__ double dred[4][6];
    double vals[6] = { aC, mm[0], mm[1], mm[2], mm[3], mm[4] };
    #pragma unroll
    for (int k = 0; k < 6; k++) {
        double v = vals[k];
        #pragma unroll
        for (int o = 16; o; o >>= 1) v += __shfl_down_sync(0xffffffffu, v, o);
        if (lane == 0) dred[wid][k] = v;
    }
    __syncthreads();
    if (tid == 0) {
        double r[6];
        #pragma unroll
        for (int k = 0; k < 6; k++) {
            double v = 0.0;
            #pragma unroll
            for (int w2 = 0; w2 < 4; w2++) v += dred[w2][k];
            r[k] = v;
        }
        double n = (double)N;
        double mse = r[1] / n;
        double pred_var = (r[3] - r[2] * r[2] / n) / (n - 1.0);
        double tgt_var  = (r[5] - r[4] * r[4] / n) / (n - 1.0);
        double div = tgt_var - pred_var;
        if (div < 0.0) div = 0.0;
        long long pc = (long long)N * (N - 1) / 2;
        if (pc < 1) pc = 1;
        double rank = 0.5 * r[0] / (double)pc;   // r[0] already = A + 0.1*B
        out[0] = (float)(0.1 * mse + 0.9 * rank + 0.1 * div);
        g_ticket = 0;  // reset for graph replay
    }
}

extern "C" void kernel_launch(void* const* d_in, const int* in_sizes, int n_in,
                              void* d_out, int out_size) {
    const float* pred = (const float*)d_in[0];
    const float* tgt  = (const float*)d_in[1];
    float* out = (float*)d_out;
    int N = in_sizes[0];
    int nt = (N + T - 1) / T;
    int nblocks = nt * (nt + 1) / 2;
    fused_kernel<<<nblocks, T>>>(pred, tgt, N, nt, out);
}

// round 8
// speedup vs baseline: 1.3378x; 1.3378x over previous
#include <cuda_runtime.h>
#include <cuda_fp16.h>
#include <cstring>

// CombinedPriorityLoss: 0.1*MSE + 0.9*pairwise-rank + 0.1*diversity
// fp16x2 engine, 256x128 tiles (2 i-rows per thread -> 2x ILP, half the LDS),
// exact-weight triangle coverage (each unordered pair weight 1),
// deterministic last-block finalize.

#define MARGIN 0.2f

constexpr int T = 128;             // threads per block == j-tile width
constexpr int MAXC = 128;          // max 128-col-tiles (N <= 16384)
constexpr int MAXR = 64;           // max 256-row-tiles
constexpr int MAXB = MAXR * MAXC;

__device__ float  g_partial[MAXB];   // combined A + 0.1*B per block
__device__ float  g_moms[MAXR][5];   // per 256-row granule: sd2, sp, spp, st, stt
__device__ unsigned g_ticket = 0;

__device__ __forceinline__ __half2 u2h(unsigned u) {
    __half2 h; memcpy(&h, &u, 4); return h;
}
__device__ __forceinline__ unsigned h2u(__half2 h) {
    unsigned u; memcpy(&u, &h, 4); return u;
}

__global__ __launch_bounds__(T)
void fused_kernel(const float* __restrict__ pred,
                  const float* __restrict__ tgt,
                  int N, int nC, float* __restrict__ out) {
    const int bid = blockIdx.x;
    const int nblocks = gridDim.x;
    const int tid = threadIdx.x;
    const int lane = tid & 31;
    const int wid  = tid >> 5;
    const int nR = (nC + 1) >> 1;

    // decode (TI, tj): row TI covers tj in [2*TI, nC); cum(TI) = TI*(nC+1-TI)
    int TI = (int)(((float)(nC + 1) -
                    sqrtf((float)((nC + 1) * (nC + 1) - 4 * bid))) * 0.5f);
    if (TI < 0) TI = 0;
    while ((TI + 1) * (nC - TI) <= bid) TI++;
    while (TI * (nC + 1 - TI) > bid) TI--;
    const int tj = 2 * TI + (bid - TI * (nC + 1 - TI));
    const int dd = tj - 2 * TI;

    // weights: each unordered pair gets total weight exactly 1.
    //   dd>=2 : all i<j           -> w0=1, w1=1
    //   dd==1 : i0<j; i1 same band as j (both-ordered sum) -> w0=1, w1=0.5
    //   dd==0 : i0 same band (0.5); i1>j are mirrors, skip -> w0=0.5, w1=0
    const float w0 = (dd == 0) ? 0.5f : 1.f;
    const float w1 = (dd == 0) ? 0.f : ((dd == 1) ? 0.5f : 1.f);

    __shared__ uint4 sP[T / 8];   // 128 x fp16(-0.1*pred[j])
    __shared__ uint4 sT[T / 8];   // 128 x fp16(-tgt[j])
    __shared__ float red[4][8];
    __shared__ int s_last;

    {
        int j = tj * T + tid;
        float pj = (j < N) ? pred[j] : 30000.f;   // finite pad -> 0 contribution
        float tv = (j < N) ? tgt[j]  : 30000.f;
        ((__half*)sP)[tid] = __float2half_rn(-0.1f * pj);
        ((__half*)sT)[tid] = __float2half_rn(-tv);
    }
    __syncthreads();

    const int i0 = TI * 256 + tid;
    const int i1 = i0 + 128;
    float p0f = (i0 < N) ? pred[i0] : 30000.f;
    float t0f = (i0 < N) ? tgt[i0]  : 30000.f;
    float p1f = (i1 < N) ? pred[i1] : 30000.f;
    float t1f = (i1 < N) ? tgt[i1]  : 30000.f;

    float accC;
    {
        const unsigned pi0 = h2u(__half2half2(__float2half_rn(0.1f * p0f)));
        const unsigned ti0 = h2u(__half2half2(__float2half_rn(t0f)));
        const unsigned pi1 = h2u(__half2half2(__float2half_rn(0.1f * p1f)));
        const unsigned ti1 = h2u(__half2half2(__float2half_rn(t1f)));

        const __half2 M2   = __float2half2_rn(MARGIN);
        const __half2 Z2   = __float2half2_rn(0.f);
        const __half2 TEN2 = __float2half2_rn(10.f);

        __half2 a0[4], a1[4];
        #pragma unroll
        for (int q = 0; q < 4; q++) { a0[q] = Z2; a1[q] = Z2; }

        // per half2 (2 pairs): dp''=0.1(pi-pj), dt=ti-tj
        // qx''=(dt>0?-dp'':dp''), r=max(10*qx''+M,0)
        // v = |dt|>M ? r : |dp''|   (|dp''| = 0.1|dp| = mid value)
        #define PAIR2(pi2, ti2, vpu, vtu, acc) {                              \
            unsigned dpu = h2u(__hadd2(u2h(pi2), u2h(vpu)));                  \
            unsigned dtu = h2u(__hadd2(u2h(ti2), u2h(vtu)));                  \
            unsigned qxu = dpu ^ 0x80008000u ^ (dtu & 0x80008000u);           \
            __half2 r2 = __hmax2(__hfma2(u2h(qxu), TEN2, M2), Z2);            \
            unsigned m = __hgt2_mask(u2h(dtu & 0x7FFF7FFFu), M2);             \
            unsigned vs = (h2u(r2) & m) | ((dpu & 0x7FFF7FFFu) & ~m);         \
            acc = __hadd2(acc, u2h(vs)); }

        #pragma unroll 4
        for (int k = 0; k < T / 8; k++) {
            uint4 vp = sP[k];
            uint4 vt = sT[k];
            PAIR2(pi0, ti0, vp.x, vt.x, a0[0]);
            PAIR2(pi0, ti0, vp.y, vt.y, a0[1]);
            PAIR2(pi0, ti0, vp.z, vt.z, a0[2]);
            PAIR2(pi0, ti0, vp.w, vt.w, a0[3]);
            PAIR2(pi1, ti1, vp.x, vt.x, a1[0]);
            PAIR2(pi1, ti1, vp.y, vt.y, a1[1]);
            PAIR2(pi1, ti1, vp.z, vt.z, a1[2]);
            PAIR2(pi1, ti1, vp.w, vt.w, a1[3]);
        }
        #undef PAIR2

        float c0 = 0.f, c1 = 0.f;
        #pragma unroll
        for (int q = 0; q < 4; q++) {
            c0 += __low2float(a0[q]) + __high2float(a0[q]);
            c1 += __low2float(a1[q]) + __high2float(a1[q]);
        }
        accC = c0 * w0 + c1 * w1;
    }

    // block reduction (4 warps)
    #pragma unroll
    for (int o = 16; o; o >>= 1)
        accC += __shfl_down_sync(0xffffffffu, accC, o);
    if (lane == 0) red[wid][0] = accC;
    __syncthreads();
    if (tid == 0) {
        float a = 0.f;
        #pragma unroll
        for (int w2 = 0; w2 < 4; w2++) a += red[w2][0];
        g_partial[bid] = a;
    }
    __syncthreads();

    // dd==0 blocks: O(N) fp32 moments for this 256-row granule (i0 and i1)
    if (dd == 0) {
        float p0 = (i0 < N) ? p0f : 0.f, t0 = (i0 < N) ? t0f : 0.f;
        float p1 = (i1 < N) ? p1f : 0.f, t1 = (i1 < N) ? t1f : 0.f;
        float d0 = p0 - t0, d1 = p1 - t1;
        float m[5] = { d0 * d0 + d1 * d1, p0 + p1, p0 * p0 + p1 * p1,
                       t0 + t1, t0 * t0 + t1 * t1 };
        #pragma unroll
        for (int k = 0; k < 5; k++) {
            float v = m[k];
            #pragma unroll
            for (int o = 16; o; o >>= 1) v += __shfl_down_sync(0xffffffffu, v, o);
            if (lane == 0) red[wid][k] = v;
        }
        __syncthreads();
        if (tid == 0) {
            #pragma unroll
            for (int k = 0; k < 5; k++) {
                float v = 0.f;
                #pragma unroll
                for (int w2 = 0; w2 < 4; w2++) v += red[w2][k];
                g_moms[TI][k] = v;
            }
        }
    }

    // ---- deterministic last-block finalize ----
    __threadfence();
    if (tid == 0) {
        unsigned t = atomicAdd(&g_ticket, 1u);
        s_last = (t == (unsigned)(nblocks - 1));
    }
    __syncthreads();
    if (!s_last) return;

    double aC = 0.0;
    for (int b = tid; b < nblocks; b += T) aC += (double)g_partial[b];
    double mm[5] = {0, 0, 0, 0, 0};
    for (int b = tid; b < nR; b += T) {
        #pragma unroll
        for (int k = 0; k < 5; k++) mm[k] += (double)g_moms[b][k];
    }

    __shared__ double dred[4][6];
    double vals[6] = { aC, mm[0], mm[1], mm[2], mm[3], mm[4] };
    #pragma unroll
    for (int k = 0; k < 6; k++) {
        double v = vals[k];
        #pragma unroll
        for (int o = 16; o; o >>= 1) v += __shfl_down_sync(0xffffffffu, v, o);
        if (lane == 0) dred[wid][k] = v;
    }
    __syncthreads();
    if (tid == 0) {
        double r[6];
        #pragma unroll
        for (int k = 0; k < 6; k++) {
            double v = 0.0;
            #pragma unroll
            for (int w2 = 0; w2 < 4; w2++) v += dred[w2][k];
            r[k] = v;
        }
        double n = (double)N;
        double mse = r[1] / n;
        double pred_var = (r[3] - r[2] * r[2] / n) / (n - 1.0);
        double tgt_var  = (r[5] - r[4] * r[4] / n) / (n - 1.0);
        double div = tgt_var - pred_var;
        if (div < 0.0) div = 0.0;
        long long pc = (long long)N * (N - 1) / 2;
        if (pc < 1) pc = 1;
        double rank = r[0] / (double)pc;   // coverage weight is exactly 1/pair
        out[0] = (float)(0.1 * mse + 0.9 * rank + 0.1 * div);
        g_ticket = 0;  // reset for graph replay
    }
}

extern "C" void kernel_launch(void* const* d_in, const int* in_sizes, int n_in,
                              void* d_out, int out_size) {
    const float* pred = (const float*)d_in[0];
    const float* tgt  = (const float*)d_in[1];
    float* out = (float*)d_out;
    int N = in_sizes[0];
    int nC = (N + T - 1) / T;          // 128-col tiles
    int nR = (nC + 1) / 2;             // 256-row tiles
    int nblocks = nR * (nC + 1 - nR);  // cum(nR)
    fused_kernel<<<nblocks, T>>>(pred, tgt, N, nC, out);
}